// round 5
// baseline (speedup 1.0000x reference)
#include <cuda_runtime.h>
#include <cuda_fp16.h>
#include <cstdint>
#include <cstddef>

// Problem constants
#define Bn 64
#define Sq 512
#define Dk 1024
#define Uo 4096
#define Ex 16

// Tiling: CTA 128x256, warp 64x64 (8 warps = 2m x 4n), 256 threads
#define BM 128
#define BN 256
#define BK 32
#define NK (Dk / BK)        // 32 K-tiles
#define NTHREADS 256
#define STAGES 4

// SMEM: halves, stride 40 per row (80 B). ldmatrix 8-row access: start banks
// (20*row) mod 32 = {0,20,8,28,16,4,24,12} -> disjoint 4-bank ranges, conflict-free.
#define ST_H 40
#define A_TILE_B (BM * ST_H * 2)               // 10240
#define B_TILE_B (BN * ST_H * 2)               // 20480
#define STG_BYTES (A_TILE_B + B_TILE_B)        // 30720
#define BIAS_OFF (STAGES * STG_BYTES)          // 122880
#define SMEM_REQ (BIAS_OFF + BN * 4)           // 123904

// Device scratch: fp16 copies (x as-is, ws transposed to [e][n][k])
__device__ __half g_wsT[(size_t)Ex * Uo * Dk];   // 128 MB
__device__ __half g_x16[(size_t)Bn * Sq * Dk];   //  64 MB

// ---------------- helpers ----------------
__device__ __forceinline__ uint32_t smem_u32(const void* p) {
    uint32_t a;
    asm("{ .reg .u64 t; cvta.to.shared.u64 t, %1; cvt.u32.u64 %0, t; }"
        : "=r"(a) : "l"(p));
    return a;
}

__device__ __forceinline__ void cp16(uint32_t saddr, const void* g) {
    asm volatile("cp.async.cg.shared.global [%0], [%1], 16;" :: "r"(saddr), "l"(g));
}
__device__ __forceinline__ void cp_commit() {
    asm volatile("cp.async.commit_group;" ::: "memory");
}
template <int N>
__device__ __forceinline__ void cp_wait() {
    asm volatile("cp.async.wait_group %0;" :: "n"(N) : "memory");
}

__device__ __forceinline__ void ldmatrix_x4(uint32_t* r, uint32_t saddr) {
    asm volatile("ldmatrix.sync.aligned.m8n8.x4.shared.b16 {%0,%1,%2,%3}, [%4];"
                 : "=r"(r[0]), "=r"(r[1]), "=r"(r[2]), "=r"(r[3]) : "r"(saddr));
}

__device__ __forceinline__ void mma_f16(float* d, const uint32_t* a,
                                        uint32_t b0, uint32_t b1) {
    asm volatile(
        "mma.sync.aligned.m16n8k16.row.col.f32.f16.f16.f32 "
        "{%0,%1,%2,%3}, {%4,%5,%6,%7}, {%8,%9}, {%0,%1,%2,%3};"
        : "+f"(d[0]), "+f"(d[1]), "+f"(d[2]), "+f"(d[3])
        : "r"(a[0]), "r"(a[1]), "r"(a[2]), "r"(a[3]), "r"(b0), "r"(b1));
}

// ---------------- pre-pass 1: ws [e][k][n] fp32 -> g_wsT [e][n][k] fp16 ----------------
__global__ void __launch_bounds__(256) transpose_h_kernel(const float* __restrict__ ws) {
    __shared__ float tile[32][33];
    const int e  = blockIdx.z;
    const int k0 = blockIdx.y * 32;
    const int n0 = blockIdx.x * 32;
    const int tx = threadIdx.x;
    const int ty = threadIdx.y;

    const float* src = ws + ((size_t)e * Dk + k0) * Uo + n0;
#pragma unroll
    for (int j = 0; j < 4; j++)
        tile[ty + j * 8][tx] = src[(size_t)(ty + j * 8) * Uo + tx];
    __syncthreads();

    __half* dst = g_wsT + ((size_t)e * Uo + n0) * Dk + k0;
#pragma unroll
    for (int j = 0; j < 4; j++)
        dst[(size_t)(ty + j * 8) * Dk + tx] = __float2half_rn(tile[tx][ty + j * 8]);
}

// ---------------- pre-pass 2: x fp32 -> fp16 ----------------
__global__ void __launch_bounds__(256) cvt_h_kernel(const float4* __restrict__ src,
                                                    uint2* __restrict__ dst, size_t n4) {
    size_t i = (size_t)blockIdx.x * blockDim.x + threadIdx.x;
    size_t stride = (size_t)gridDim.x * blockDim.x;
    for (; i < n4; i += stride) {
        float4 v = src[i];
        __half2 lo = __floats2half2_rn(v.x, v.y);
        __half2 hi = __floats2half2_rn(v.z, v.w);
        uint2 o;
        o.x = *reinterpret_cast<uint32_t*>(&lo);
        o.y = *reinterpret_cast<uint32_t*>(&hi);
        dst[i] = o;
    }
}

// ---------------- main GEMM ----------------
__global__ void __launch_bounds__(NTHREADS)
indexed_dense_gemm(const float* __restrict__ bs, const int* __restrict__ index,
                   float* __restrict__ out) {
    extern __shared__ char smem[];
    const uint32_t sbase = smem_u32(smem);
    float* const smf = reinterpret_cast<float*>(smem);

    const int tid   = threadIdx.x;
    const int batch = blockIdx.z;
    const int m0    = blockIdx.y * BM;
    const int n0    = blockIdx.x * BN;
    const int e     = index[batch];

    smf[BIAS_OFF / 4 + tid] = bs[(size_t)e * Uo + n0 + tid];

    const __half* __restrict__ xg = g_x16 + ((size_t)batch * Sq + m0) * Dk;  // [m][k]
    const __half* __restrict__ wg = g_wsT + ((size_t)e * Uo + n0) * Dk;      // [n][k]

    // cp.async coordinates: 16B chunks (8 halves); 4 chunks per 64B k-row
    const int ar  = tid >> 2;
    const int ac4 = tid & 3;
    const uint32_t a_s0 = sbase + (uint32_t)(ar * 80 + ac4 * 16);
    const uint32_t b_s0 = sbase + A_TILE_B + (uint32_t)(ar * 80 + ac4 * 16);

    auto load_stage = [&](int kt, int s) {
        const uint32_t so = (uint32_t)s * STG_BYTES;
        const __half* ag = xg + (size_t)ar * Dk + kt * BK + ac4 * 8;
        const __half* bg = wg + (size_t)ar * Dk + kt * BK + ac4 * 8;
#pragma unroll
        for (int j = 0; j < 2; j++)
            cp16(a_s0 + so + j * 64 * 80, ag + (size_t)j * 64 * Dk);
#pragma unroll
        for (int j = 0; j < 4; j++)
            cp16(b_s0 + so + j * 64 * 80, bg + (size_t)j * 64 * Dk);
    };

    load_stage(0, 0); cp_commit();
    load_stage(1, 1); cp_commit();
    load_stage(2, 2); cp_commit();

    // warp tiling: 8 warps = 2 (m) x 4 (n); warp tile 64 x 64
    const int warp = tid >> 5;
    const int lane = tid & 31;
    const int wm   = (warp >> 2) * 64;
    const int wn   = (warp & 3) * 64;
    const int r    = lane >> 2;
    const int c    = lane & 3;

    // ldmatrix lane address pattern: tile t = lane>>3, row p = lane&7
    // addr(base_row) = (base_row + (t&1)*8 + p)*ST_H + (t>>1)*8   [halves]
    const int lm_t = lane >> 3;
    const int lm_p = lane & 7;
    const uint32_t lm_row_add = (uint32_t)(((lm_t & 1) * 8 + lm_p) * ST_H + (lm_t >> 1) * 8) * 2;
    // A fragment base for mi=0 (row wm), B fragment base for j=0 (row wn)
    const uint32_t a_lm0 = sbase + (uint32_t)(wm * ST_H) * 2 + lm_row_add;
    const uint32_t b_lm0 = sbase + A_TILE_B + (uint32_t)(wn * ST_H) * 2 + lm_row_add;

    float d[4][8][4];
#pragma unroll
    for (int mi = 0; mi < 4; mi++)
#pragma unroll
        for (int ni = 0; ni < 8; ni++)
#pragma unroll
            for (int j = 0; j < 4; j++) d[mi][ni][j] = 0.0f;

#pragma unroll 1
    for (int kt = 0; kt < NK; kt++) {
        cp_wait<2>();
        __syncthreads();

        if (kt + 3 < NK) load_stage(kt + 3, (kt + 3) & (STAGES - 1));
        cp_commit();

        const uint32_t so = (uint32_t)(kt & (STAGES - 1)) * STG_BYTES;

#pragma unroll
        for (int ks = 0; ks < 2; ks++) {
            const uint32_t ko = (uint32_t)(ks * 16) * 2;   // byte offset in k
            uint32_t a[4][4];
#pragma unroll
            for (int mi = 0; mi < 4; mi++)
                ldmatrix_x4(a[mi], a_lm0 + so + ko + (uint32_t)(mi * 16 * ST_H) * 2);
            uint32_t b[4][4];  // b[j]: {b[2j][0], b[2j+1][0], b[2j][1], b[2j+1][1]}
#pragma unroll
            for (int j = 0; j < 4; j++)
                ldmatrix_x4(b[j], b_lm0 + so + ko + (uint32_t)(j * 16 * ST_H) * 2);
#pragma unroll
            for (int mi = 0; mi < 4; mi++)
#pragma unroll
                for (int j = 0; j < 4; j++) {
                    mma_f16(d[mi][2 * j + 0], a[mi], b[j][0], b[j][2]);
                    mma_f16(d[mi][2 * j + 1], a[mi], b[j][1], b[j][3]);
                }
        }
    }

    // epilogue: bias + relu + float2 stores
    const float* bias_s = smf + BIAS_OFF / 4 + wn;
#pragma unroll
    for (int mi = 0; mi < 4; mi++) {
#pragma unroll
        for (int rr = 0; rr < 2; rr++) {
            const int m = m0 + wm + mi * 16 + rr * 8 + r;
            float* op = out + ((size_t)batch * Sq + m) * Uo + n0 + wn;
#pragma unroll
            for (int ni = 0; ni < 8; ni++) {
                const int nl = ni * 8 + 2 * c;
                float2 v;
                v.x = fmaxf(d[mi][ni][2 * rr + 0] + bias_s[nl + 0], 0.0f);
                v.y = fmaxf(d[mi][ni][2 * rr + 1] + bias_s[nl + 1], 0.0f);
                *reinterpret_cast<float2*>(op + nl) = v;
            }
        }
    }
}

// ---------------- launch ----------------
extern "C" void kernel_launch(void* const* d_in, const int* in_sizes, int n_in,
                              void* d_out, int out_size) {
    const float* x     = (const float*)d_in[0];
    const float* ws    = (const float*)d_in[1];
    const float* bs    = (const float*)d_in[2];
    const int*   index = (const int*)d_in[3];
    float*       out   = (float*)d_out;
    (void)in_sizes; (void)n_in; (void)out_size;

    __half* x16_ptr = nullptr;
    cudaGetSymbolAddress((void**)&x16_ptr, g_x16);

    transpose_h_kernel<<<dim3(Uo / 32, Dk / 32, Ex), dim3(32, 8)>>>(ws);
    const size_t x_n4 = (size_t)Bn * Sq * Dk / 4;
    cvt_h_kernel<<<4096, 256>>>((const float4*)x, (uint2*)x16_ptr, x_n4);

    static bool attr_set = false;
    if (!attr_set) {
        cudaFuncSetAttribute(indexed_dense_gemm,
                             cudaFuncAttributeMaxDynamicSharedMemorySize, SMEM_REQ);
        attr_set = true;
    }

    indexed_dense_gemm<<<dim3(Uo / BN, Sq / BM, Bn), NTHREADS, SMEM_REQ>>>(bs, index, out);
}

// round 6
// speedup vs baseline: 1.0604x; 1.0604x over previous
#include <cuda_runtime.h>
#include <cuda_fp16.h>
#include <cstdint>
#include <cstddef>

// Problem constants
#define Bn 64
#define Sq 512
#define Dk 1024
#define Uo 4096
#define Ex 16

// Tiling: CTA 128x256, warp 64x64 (8 warps = 2m x 4n), 256 threads
#define BM 128
#define BN 256
#define BK 32
#define NK (Dk / BK)        // 32 K-tiles
#define NTHREADS 256
#define STAGES 4

// SMEM: halves, stride 40 per row (80 B) -> conflict-free fragment LDS
#define ST_H 40
#define A_TILE_B (BM * ST_H * 2)               // 10240
#define B_TILE_B (BN * ST_H * 2)               // 20480
#define STG_BYTES (A_TILE_B + B_TILE_B)        // 30720
#define BIAS_OFF (STAGES * STG_BYTES)          // 122880
#define SMEM_REQ (BIAS_OFF + BN * 4)           // 123904

// Device scratch: fp16 copies (x as-is, ws transposed to [e][n][k])
__device__ __half g_wsT[(size_t)Ex * Uo * Dk];   // 128 MB
__device__ __half g_x16[(size_t)Bn * Sq * Dk];   //  64 MB

// ---------------- helpers ----------------
__device__ __forceinline__ uint32_t smem_u32(const void* p) {
    uint32_t a;
    asm("{ .reg .u64 t; cvta.to.shared.u64 t, %1; cvt.u32.u64 %0, t; }"
        : "=r"(a) : "l"(p));
    return a;
}

__device__ __forceinline__ void cp16(uint32_t saddr, const void* g) {
    asm volatile("cp.async.cg.shared.global [%0], [%1], 16;" :: "r"(saddr), "l"(g));
}
__device__ __forceinline__ void cp_commit() {
    asm volatile("cp.async.commit_group;" ::: "memory");
}
template <int N>
__device__ __forceinline__ void cp_wait() {
    asm volatile("cp.async.wait_group %0;" :: "n"(N) : "memory");
}

__device__ __forceinline__ void mma_f16(float* d, const uint32_t* a, const uint32_t* b) {
    asm volatile(
        "mma.sync.aligned.m16n8k16.row.col.f32.f16.f16.f32 "
        "{%0,%1,%2,%3}, {%4,%5,%6,%7}, {%8,%9}, {%0,%1,%2,%3};"
        : "+f"(d[0]), "+f"(d[1]), "+f"(d[2]), "+f"(d[3])
        : "r"(a[0]), "r"(a[1]), "r"(a[2]), "r"(a[3]), "r"(b[0]), "r"(b[1]));
}

__device__ __forceinline__ void stcs8(float* p, float2 v) {
    asm volatile("st.global.cs.v2.f32 [%0], {%1, %2};" :: "l"(p), "f"(v.x), "f"(v.y)
                 : "memory");
}

// ---------------- pre-pass 1: ws [e][k][n] fp32 -> g_wsT [e][n][k] fp16 ----------------
// 64k x 32n tiles: reads 128B-coalesced, writes full 128B lines (8 x uint4 per n-row).
__global__ void __launch_bounds__(256) transpose_h_kernel(const float* __restrict__ ws) {
    __shared__ __half tileT[32][72];   // row stride 144B (16B-aligned rows)
    const int e  = blockIdx.z;
    const int k0 = blockIdx.y * 64;
    const int n0 = blockIdx.x * 32;
    const int t  = threadIdx.x;

    const float* src = ws + ((size_t)e * Dk + k0) * Uo + n0;
    const int kr = t >> 3;       // 0..31
    const int c4 = t & 7;        // float4 chunk in n
#pragma unroll
    for (int p = 0; p < 2; p++) {
        const int k = kr + p * 32;
        float4 v = *reinterpret_cast<const float4*>(src + (size_t)k * Uo + c4 * 4);
        tileT[c4 * 4 + 0][k] = __float2half_rn(v.x);
        tileT[c4 * 4 + 1][k] = __float2half_rn(v.y);
        tileT[c4 * 4 + 2][k] = __float2half_rn(v.z);
        tileT[c4 * 4 + 3][k] = __float2half_rn(v.w);
    }
    __syncthreads();

    const int n = t >> 3;        // 0..31
    const int j = t & 7;         // 16B chunk in k
    __half* dst = g_wsT + ((size_t)e * Uo + n0 + n) * Dk + k0;
    *reinterpret_cast<uint4*>(dst + j * 8) =
        *reinterpret_cast<const uint4*>(&tileT[n][j * 8]);
}

// ---------------- pre-pass 2: x fp32 -> fp16 ----------------
__global__ void __launch_bounds__(256) cvt_h_kernel(const float4* __restrict__ src,
                                                    uint2* __restrict__ dst, size_t n4) {
    size_t i = (size_t)blockIdx.x * blockDim.x + threadIdx.x;
    size_t stride = (size_t)gridDim.x * blockDim.x;
    for (; i < n4; i += stride) {
        float4 v = src[i];
        __half2 lo = __floats2half2_rn(v.x, v.y);
        __half2 hi = __floats2half2_rn(v.z, v.w);
        uint2 o;
        o.x = *reinterpret_cast<uint32_t*>(&lo);
        o.y = *reinterpret_cast<uint32_t*>(&hi);
        dst[i] = o;
    }
}

// ---------------- main GEMM (round-4 proven mainloop) ----------------
__global__ void __launch_bounds__(NTHREADS)
indexed_dense_gemm(const float* __restrict__ bs, const int* __restrict__ index,
                   float* __restrict__ out) {
    extern __shared__ char smem[];
    const uint32_t sbase = smem_u32(smem);
    float* const smf = reinterpret_cast<float*>(smem);

    const int tid   = threadIdx.x;
    const int batch = blockIdx.z;
    const int m0    = blockIdx.y * BM;
    const int n0    = blockIdx.x * BN;
    const int e     = index[batch];

    smf[BIAS_OFF / 4 + tid] = bs[(size_t)e * Uo + n0 + tid];

    const __half* __restrict__ xg = g_x16 + ((size_t)batch * Sq + m0) * Dk;  // [m][k]
    const __half* __restrict__ wg = g_wsT + ((size_t)e * Uo + n0) * Dk;      // [n][k]

    const int ar  = tid >> 2;
    const int ac4 = tid & 3;
    const uint32_t a_s0 = sbase + (uint32_t)(ar * 80 + ac4 * 16);
    const uint32_t b_s0 = sbase + A_TILE_B + (uint32_t)(ar * 80 + ac4 * 16);

    auto load_stage = [&](int kt, int s) {
        const uint32_t so = (uint32_t)s * STG_BYTES;
        const __half* ag = xg + (size_t)ar * Dk + kt * BK + ac4 * 8;
        const __half* bg = wg + (size_t)ar * Dk + kt * BK + ac4 * 8;
#pragma unroll
        for (int j = 0; j < 2; j++)
            cp16(a_s0 + so + j * 64 * 80, ag + (size_t)j * 64 * Dk);
#pragma unroll
        for (int j = 0; j < 4; j++)
            cp16(b_s0 + so + j * 64 * 80, bg + (size_t)j * 64 * Dk);
    };

    load_stage(0, 0); cp_commit();
    load_stage(1, 1); cp_commit();
    load_stage(2, 2); cp_commit();

    const int warp = tid >> 5;
    const int lane = tid & 31;
    const int wm   = (warp >> 2) * 64;
    const int wn   = (warp & 3) * 64;
    const int r    = lane >> 2;
    const int c    = lane & 3;

    float d[4][8][4];
#pragma unroll
    for (int mi = 0; mi < 4; mi++)
#pragma unroll
        for (int ni = 0; ni < 8; ni++)
#pragma unroll
            for (int j = 0; j < 4; j++) d[mi][ni][j] = 0.0f;

#pragma unroll 1
    for (int kt = 0; kt < NK; kt++) {
        cp_wait<2>();
        __syncthreads();

        if (kt + 3 < NK) load_stage(kt + 3, (kt + 3) & (STAGES - 1));
        cp_commit();

        const __half* sa = reinterpret_cast<const __half*>(
            smem + (size_t)(kt & (STAGES - 1)) * STG_BYTES);
        const __half* sb = sa + BM * ST_H;

#pragma unroll
        for (int ks = 0; ks < 2; ks++) {
            const int k = ks * 16;
            uint32_t a[4][4];
#pragma unroll
            for (int mi = 0; mi < 4; mi++) {
                const int row = wm + mi * 16 + r;
                a[mi][0] = *reinterpret_cast<const uint32_t*>(&sa[(size_t)row * ST_H + k + 2 * c]);
                a[mi][1] = *reinterpret_cast<const uint32_t*>(&sa[(size_t)(row + 8) * ST_H + k + 2 * c]);
                a[mi][2] = *reinterpret_cast<const uint32_t*>(&sa[(size_t)row * ST_H + k + 2 * c + 8]);
                a[mi][3] = *reinterpret_cast<const uint32_t*>(&sa[(size_t)(row + 8) * ST_H + k + 2 * c + 8]);
            }
            uint32_t b[8][2];
#pragma unroll
            for (int ni = 0; ni < 8; ni++) {
                const int col = wn + ni * 8 + r;
                b[ni][0] = *reinterpret_cast<const uint32_t*>(&sb[(size_t)col * ST_H + k + 2 * c]);
                b[ni][1] = *reinterpret_cast<const uint32_t*>(&sb[(size_t)col * ST_H + k + 2 * c + 8]);
            }
#pragma unroll
            for (int mi = 0; mi < 4; mi++)
#pragma unroll
                for (int ni = 0; ni < 8; ni++)
                    mma_f16(d[mi][ni], a[mi], b[ni]);
        }
    }

    // epilogue: bias + relu + streaming float2 stores (keep L2 for weights)
    const float* bias_s = smf + BIAS_OFF / 4 + wn;
#pragma unroll
    for (int mi = 0; mi < 4; mi++) {
#pragma unroll
        for (int rr = 0; rr < 2; rr++) {
            const int m = m0 + wm + mi * 16 + rr * 8 + r;
            float* op = out + ((size_t)batch * Sq + m) * Uo + n0 + wn;
#pragma unroll
            for (int ni = 0; ni < 8; ni++) {
                const int nl = ni * 8 + 2 * c;
                float2 v;
                v.x = fmaxf(d[mi][ni][2 * rr + 0] + bias_s[nl + 0], 0.0f);
                v.y = fmaxf(d[mi][ni][2 * rr + 1] + bias_s[nl + 1], 0.0f);
                stcs8(op + nl, v);
            }
        }
    }
}

// ---------------- launch ----------------
extern "C" void kernel_launch(void* const* d_in, const int* in_sizes, int n_in,
                              void* d_out, int out_size) {
    const float* x     = (const float*)d_in[0];
    const float* ws    = (const float*)d_in[1];
    const float* bs    = (const float*)d_in[2];
    const int*   index = (const int*)d_in[3];
    float*       out   = (float*)d_out;
    (void)in_sizes; (void)n_in; (void)out_size;

    __half* x16_ptr = nullptr;
    cudaGetSymbolAddress((void**)&x16_ptr, g_x16);

    transpose_h_kernel<<<dim3(Uo / 32, Dk / 64, Ex), 256>>>(ws);
    const size_t x_n4 = (size_t)Bn * Sq * Dk / 4;
    cvt_h_kernel<<<4096, 256>>>((const float4*)x, (uint2*)x16_ptr, x_n4);

    static bool attr_set = false;
    if (!attr_set) {
        cudaFuncSetAttribute(indexed_dense_gemm,
                             cudaFuncAttributeMaxDynamicSharedMemorySize, SMEM_REQ);
        attr_set = true;
    }

    indexed_dense_gemm<<<dim3(Uo / BN, Sq / BM, Bn), NTHREADS, SMEM_REQ>>>(bs, index, out);
}